// round 13
// baseline (speedup 1.0000x reference)
#include <cuda_runtime.h>

// B=16, C=4, H=1024, W=1024
// x: [B, C, H, W] fp32 ; out: [B, H, C, W] fp32
//
// Two-tile pipelined moment kernel. 8192 CTAs x 256 threads; CTA n handles
// bh0 = n (b in 0..7) and bh1 = n + 8192 (b in 8..15).
// All 8 float4 loads (both tiles) are issued up front; tile 1's reduce /
// epilogue / store runs while tile 2's loads are in flight, so the CTA's
// DRAM demand stays nonzero through the reduction window, and tile 2's
// latency is fully hidden under tile 1's compute.
// Per tile: butterfly (16 SHFL) -> s_red[t] -> ONE __syncthreads ->
// warp-redundant epilogue (scores/softmax/A_eff via SHFL) -> float4 stores.

#define H_DIM 1024
#define W_DIM 1024
#define THREADS 256

__global__ __launch_bounds__(THREADS, 3)
void fused_attn_kernel(const float* __restrict__ x,
                       const float* __restrict__ wq, const float* __restrict__ bq,
                       const float* __restrict__ wk, const float* __restrict__ bk,
                       const float* __restrict__ wv, const float* __restrict__ bv,
                       float* __restrict__ out)
{
    const int tid  = threadIdx.x;
    const int lane = tid & 31;
    const int warp = tid >> 5;
    const int w0   = tid << 2;

    __shared__ float s_red[2][8][16];   // double-buffered per-warp partials

    const int bh0 = blockIdx.x;          // b in 0..7
    const int bh1 = blockIdx.x + 8192;   // b in 8..15

    // ---- Front-batch ALL 8 loads (tile0 then tile1), streaming
    float xv[2][4][4];
    #pragma unroll
    for (int t = 0; t < 2; t++) {
        const int bh = t ? bh1 : bh0;
        const int b = bh >> 10;
        const int h = bh & (H_DIM - 1);
        const int base = ((b << 2) * H_DIM + h) * W_DIM + w0;
        #pragma unroll
        for (int c = 0; c < 4; c++) {
            const float4 v = __ldcs(reinterpret_cast<const float4*>(
                                  x + base + c * (H_DIM * W_DIM)));
            xv[t][c][0] = v.x; xv[t][c][1] = v.y;
            xv[t][c][2] = v.z; xv[t][c][3] = v.w;
        }
    }

    #pragma unroll
    for (int t = 0; t < 2; t++) {
        const int bh = t ? bh1 : bh0;

        // ---- Moments: r = {G00,G01,G02,G03,G11,G12,G13,G22,G23,G33, m0..m3, 0,0}
        float r[16];
        #pragma unroll
        for (int i = 0; i < 16; i++) r[i] = 0.f;

        #pragma unroll
        for (int p = 0; p < 4; p++) {
            const float x0 = xv[t][0][p], x1 = xv[t][1][p];
            const float x2 = xv[t][2][p], x3 = xv[t][3][p];
            r[0] = fmaf(x0, x0, r[0]);
            r[1] = fmaf(x0, x1, r[1]);
            r[2] = fmaf(x0, x2, r[2]);
            r[3] = fmaf(x0, x3, r[3]);
            r[4] = fmaf(x1, x1, r[4]);
            r[5] = fmaf(x1, x2, r[5]);
            r[6] = fmaf(x1, x3, r[6]);
            r[7] = fmaf(x2, x2, r[7]);
            r[8] = fmaf(x2, x3, r[8]);
            r[9] = fmaf(x3, x3, r[9]);
            r[10] += x0; r[11] += x1; r[12] += x2; r[13] += x3;
        }

        // ---- Interleaved butterfly: 16 values over 32 lanes in 16 SHFL
        #pragma unroll
        for (int i = 0; i < 8; i++) {
            const float a = r[i], bb = r[i + 8];
            const float send = (lane & 16) ? a : bb;
            const float recv = __shfl_xor_sync(0xFFFFFFFFu, send, 16);
            r[i] = ((lane & 16) ? bb : a) + recv;
        }
        #pragma unroll
        for (int i = 0; i < 4; i++) {
            const float a = r[i], bb = r[i + 4];
            const float send = (lane & 8) ? a : bb;
            const float recv = __shfl_xor_sync(0xFFFFFFFFu, send, 8);
            r[i] = ((lane & 8) ? bb : a) + recv;
        }
        #pragma unroll
        for (int i = 0; i < 2; i++) {
            const float a = r[i], bb = r[i + 2];
            const float send = (lane & 4) ? a : bb;
            const float recv = __shfl_xor_sync(0xFFFFFFFFu, send, 4);
            r[i] = ((lane & 4) ? bb : a) + recv;
        }
        {
            const float a = r[0], bb = r[1];
            const float send = (lane & 2) ? a : bb;
            const float recv = __shfl_xor_sync(0xFFFFFFFFu, send, 2);
            r[0] = ((lane & 2) ? bb : a) + recv;
        }
        r[0] += __shfl_xor_sync(0xFFFFFFFFu, r[0], 1);
        if (!(lane & 1)) s_red[t][warp][(lane >> 1) & 15] = r[0];

        __syncthreads();   // one barrier per tile (buffers are distinct)

        // ---- Warp-redundant epilogue
        float gmv = 0.f;
        if (lane < 16) {
            #pragma unroll
            for (int wdx = 0; wdx < 8; wdx++) gmv += s_red[t][wdx][lane];
        }
        float g[14];
        #pragma unroll
        for (int j = 0; j < 14; j++) g[j] = __shfl_sync(0xFFFFFFFFu, gmv, j);

        float attn = 0.f;
        {
            const int c = (lane >> 2) & 3, d = lane & 3;
            float wqc[4], wkd[4];
            #pragma unroll
            for (int i = 0; i < 4; i++) {
                wqc[i] = __ldg(wq + c * 4 + i);
                wkd[i] = __ldg(wk + d * 4 + i);
            }
            const float bqc = __ldg(bq + c), bkd = __ldg(bk + d);

            float s = 0.f;
            #pragma unroll
            for (int i = 0; i < 4; i++) {
                float acc = 0.f;
                #pragma unroll
                for (int j = 0; j < 4; j++) {
                    const int lo = i < j ? i : j, hi = i < j ? j : i;
                    const int gi = lo * 4 - (lo * (lo - 1)) / 2 + (hi - lo);
                    acc = fmaf(g[gi], wkd[j], acc);
                }
                s = fmaf(wqc[i], acc, s);
            }
            const float tq = wqc[0]*g[10] + wqc[1]*g[11] + wqc[2]*g[12] + wqc[3]*g[13];
            const float tk = wkd[0]*g[10] + wkd[1]*g[11] + wkd[2]*g[12] + wkd[3]*g[13];
            s += bqc * tk + bkd * tq + (float)W_DIM * bqc * bkd;
            s *= 0.03125f;   // 1/sqrt(1024)

            float m = s;
            m = fmaxf(m, __shfl_xor_sync(0xFFFFFFFFu, m, 1));
            m = fmaxf(m, __shfl_xor_sync(0xFFFFFFFFu, m, 2));
            const float e = __expf(s - m);
            float sum = e;
            sum += __shfl_xor_sync(0xFFFFFFFFu, sum, 1);
            sum += __shfl_xor_sync(0xFFFFFFFFu, sum, 2);
            attn = e * __fdividef(1.0f, sum);
        }

        float ae_mine = 0.f, be_mine = 0.f;
        {
            const int i = lane & 3;
            const int grp = lane & ~3;
            #pragma unroll
            for (int d = 0; d < 4; d++) {
                const float ad = __shfl_sync(0xFFFFFFFFu, attn, grp + d);
                ae_mine = fmaf(ad, __ldg(wv + d * 4 + i), ae_mine);
                be_mine = fmaf(ad, __ldg(bv + d), be_mine);
            }
        }

        float ae[4][4], be[4];
        #pragma unroll
        for (int idx = 0; idx < 16; idx++)
            ae[idx >> 2][idx & 3] = __shfl_sync(0xFFFFFFFFu, ae_mine, idx);
        #pragma unroll
        for (int c = 0; c < 4; c++)
            be[c] = __shfl_sync(0xFFFFFFFFu, be_mine, c << 2);

        // ---- Store: out[c][w] = A_eff[c]·x[:,w] + b_eff[c]
        const int obase = (bh << 12) + w0;
        #pragma unroll
        for (int c = 0; c < 4; c++) {
            float4 rr;
            float* rp = &rr.x;
            #pragma unroll
            for (int j = 0; j < 4; j++) {
                float s = be[c];
                #pragma unroll
                for (int i = 0; i < 4; i++)
                    s = fmaf(ae[c][i], xv[t][i][j], s);
                rp[j] = s;
            }
            __stcs(reinterpret_cast<float4*>(out + obase + (c << 10)), rr);
        }
    }
}

extern "C" void kernel_launch(void* const* d_in, const int* in_sizes, int n_in,
                              void* d_out, int out_size)
{
    const float* x  = (const float*)d_in[0];
    const float* wq = (const float*)d_in[1];
    const float* bq = (const float*)d_in[2];
    const float* wk = (const float*)d_in[3];
    const float* bk = (const float*)d_in[4];
    const float* wv = (const float*)d_in[5];
    const float* bv = (const float*)d_in[6];
    float* out = (float*)d_out;

    dim3 grid(8192);          // two (b,h) tiles per CTA
    dim3 block(THREADS);
    fused_attn_kernel<<<grid, block>>>(x, wq, bq, wk, bk, wv, bv, out);
}

// round 14
// speedup vs baseline: 1.1320x; 1.1320x over previous
#include <cuda_runtime.h>

// B=16, C=4, H=1024, W=1024
// x: [B, C, H, W] fp32 ; out: [B, H, C, W] fp32
//
// R4-structure, register-lean via smem staging of x.
// One CTA per (b,h), 256 threads x 4 w. Loads are per-thread __ldcs float4
// (the proven best load path); x is immediately stashed to smem so the
// register peak stays <= 40 -> 6 CTAs/SM (75% occ) without spills.
//   Phase 1: load t[4], accumulate moments from t, STS t -> xt.
//   Butterfly (16 SHFL) -> s_red -> sync -> warp0 epilogue -> s_fin -> sync.
//   Phase 2: LDS x back, out = A_eff x + b_eff, streaming float4 stores.

#define H_DIM 1024
#define W_DIM 1024
#define THREADS 256

__global__ __launch_bounds__(THREADS, 6)
void fused_attn_kernel(const float* __restrict__ x,
                       const float* __restrict__ wq, const float* __restrict__ bq,
                       const float* __restrict__ wk, const float* __restrict__ bk,
                       const float* __restrict__ wv, const float* __restrict__ bv,
                       float* __restrict__ out)
{
    const int bh   = blockIdx.x;
    const int tid  = threadIdx.x;
    const int lane = tid & 31;
    const int warp = tid >> 5;
    const int w0   = tid << 2;

    __shared__ float xt[4][W_DIM];     // 16KB staged x tile
    __shared__ float s_red[8][16];     // per-warp reduced {G[10], m[4], 0,0}
    __shared__ float s_fin[20];        // A_eff[16] | b_eff[4]
    __shared__ float s_gm[16];
    __shared__ float s_sc[16];
    __shared__ float s_attn[16];

    // ---- Load x (streaming LDG.128), accumulate moments, stash to smem
    const int b = bh >> 10;
    const int h = bh & (H_DIM - 1);
    const int base = ((b << 2) * H_DIM + h) * W_DIM + w0;

    float r[16];
    #pragma unroll
    for (int i = 0; i < 16; i++) r[i] = 0.f;

    {
        float4 t[4];
        #pragma unroll
        for (int c = 0; c < 4; c++)
            t[c] = __ldcs(reinterpret_cast<const float4*>(
                       x + base + c * (H_DIM * W_DIM)));

        #pragma unroll
        for (int p = 0; p < 4; p++) {
            const float x0 = (&t[0].x)[p];
            const float x1 = (&t[1].x)[p];
            const float x2 = (&t[2].x)[p];
            const float x3 = (&t[3].x)[p];
            r[0] = fmaf(x0, x0, r[0]);
            r[1] = fmaf(x0, x1, r[1]);
            r[2] = fmaf(x0, x2, r[2]);
            r[3] = fmaf(x0, x3, r[3]);
            r[4] = fmaf(x1, x1, r[4]);
            r[5] = fmaf(x1, x2, r[5]);
            r[6] = fmaf(x1, x3, r[6]);
            r[7] = fmaf(x2, x2, r[7]);
            r[8] = fmaf(x2, x3, r[8]);
            r[9] = fmaf(x3, x3, r[9]);
            r[10] += x0; r[11] += x1; r[12] += x2; r[13] += x3;
        }

        #pragma unroll
        for (int c = 0; c < 4; c++)
            *reinterpret_cast<float4*>(&xt[c][w0]) = t[c];
    }   // t dies here -> register peak drops

    // ---- Interleaved butterfly: 16 values over 32 lanes in 16 SHFL
    #pragma unroll
    for (int i = 0; i < 8; i++) {
        const float a = r[i], bb = r[i + 8];
        const float send = (lane & 16) ? a : bb;
        const float recv = __shfl_xor_sync(0xFFFFFFFFu, send, 16);
        r[i] = ((lane & 16) ? bb : a) + recv;
    }
    #pragma unroll
    for (int i = 0; i < 4; i++) {
        const float a = r[i], bb = r[i + 4];
        const float send = (lane & 8) ? a : bb;
        const float recv = __shfl_xor_sync(0xFFFFFFFFu, send, 8);
        r[i] = ((lane & 8) ? bb : a) + recv;
    }
    #pragma unroll
    for (int i = 0; i < 2; i++) {
        const float a = r[i], bb = r[i + 2];
        const float send = (lane & 4) ? a : bb;
        const float recv = __shfl_xor_sync(0xFFFFFFFFu, send, 4);
        r[i] = ((lane & 4) ? bb : a) + recv;
    }
    {
        const float a = r[0], bb = r[1];
        const float send = (lane & 2) ? a : bb;
        const float recv = __shfl_xor_sync(0xFFFFFFFFu, send, 2);
        r[0] = ((lane & 2) ? bb : a) + recv;
    }
    r[0] += __shfl_xor_sync(0xFFFFFFFFu, r[0], 1);
    if (!(lane & 1)) s_red[warp][(lane >> 1) & 15] = r[0];
    __syncthreads();

    // ---- Epilogue: warp 0 (lean SHFL count; smem broadcast)
    if (warp == 0) {
        if (lane < 16) {
            float s = 0.f;
            #pragma unroll
            for (int wdx = 0; wdx < 8; wdx++) s += s_red[wdx][lane];
            s_gm[lane] = s;
        }
        __syncwarp();

        if (lane < 16) {
            const int c = lane >> 2, d = lane & 3;
            const float m0 = s_gm[10], m1 = s_gm[11], m2 = s_gm[12], m3 = s_gm[13];
            float wqc[4], wkd[4];
            #pragma unroll
            for (int i = 0; i < 4; i++) { wqc[i] = __ldg(wq + c * 4 + i); wkd[i] = __ldg(wk + d * 4 + i); }
            const float bqc = __ldg(bq + c), bkd = __ldg(bk + d);

            float s = 0.f;
            #pragma unroll
            for (int i = 0; i < 4; i++) {
                float acc = 0.f;
                #pragma unroll
                for (int j = 0; j < 4; j++) {
                    const int lo = i < j ? i : j, hi = i < j ? j : i;
                    const int gi = lo * 4 - (lo * (lo - 1)) / 2 + (hi - lo);
                    acc = fmaf(s_gm[gi], wkd[j], acc);
                }
                s = fmaf(wqc[i], acc, s);
            }
            const float tq = wqc[0]*m0 + wqc[1]*m1 + wqc[2]*m2 + wqc[3]*m3;
            const float tk = wkd[0]*m0 + wkd[1]*m1 + wkd[2]*m2 + wkd[3]*m3;
            s += bqc * tk + bkd * tq + (float)W_DIM * bqc * bkd;
            s_sc[lane] = s * 0.03125f;       // 1/sqrt(1024)
        }
        __syncwarp();

        if (lane < 4) {
            const int c = lane;
            float m = s_sc[c * 4];
            #pragma unroll
            for (int d = 1; d < 4; d++) m = fmaxf(m, s_sc[c * 4 + d]);
            float e[4], sum = 0.f;
            #pragma unroll
            for (int d = 0; d < 4; d++) { e[d] = __expf(s_sc[c * 4 + d] - m); sum += e[d]; }
            const float inv = __fdividef(1.0f, sum);
            #pragma unroll
            for (int d = 0; d < 4; d++) s_attn[c * 4 + d] = e[d] * inv;
        }
        __syncwarp();

        if (lane < 16) {
            const int c = lane >> 2, i = lane & 3;
            float s = 0.f;
            #pragma unroll
            for (int d = 0; d < 4; d++) s = fmaf(s_attn[c * 4 + d], __ldg(wv + d * 4 + i), s);
            s_fin[lane] = s;
        }
        if (lane < 4) {
            float s = 0.f;
            #pragma unroll
            for (int d = 0; d < 4; d++) s = fmaf(s_attn[lane * 4 + d], __ldg(bv + d), s);
            s_fin[16 + lane] = s;
        }
    }
    __syncthreads();

    // ---- Phase 2: re-read x from smem, out[c][w] = A_eff[c]·x[:,w] + b_eff[c]
    float ae[4][4], be[4];
    #pragma unroll
    for (int c = 0; c < 4; c++) {
        be[c] = s_fin[16 + c];
        #pragma unroll
        for (int i = 0; i < 4; i++) ae[c][i] = s_fin[c * 4 + i];
    }

    float4 xc[4];
    #pragma unroll
    for (int c = 0; c < 4; c++)
        xc[c] = *reinterpret_cast<const float4*>(&xt[c][w0]);

    const int obase = (bh << 12) + w0;
    #pragma unroll
    for (int c = 0; c < 4; c++) {
        float4 rr;
        float* rp = &rr.x;
        #pragma unroll
        for (int j = 0; j < 4; j++) {
            float s = be[c];
            #pragma unroll
            for (int i = 0; i < 4; i++)
                s = fmaf(ae[c][i], (&xc[i].x)[j], s);
            rp[j] = s;
        }
        __stcs(reinterpret_cast<float4*>(out + obase + (c << 10)), rr);
    }
}

extern "C" void kernel_launch(void* const* d_in, const int* in_sizes, int n_in,
                              void* d_out, int out_size)
{
    const float* x  = (const float*)d_in[0];
    const float* wq = (const float*)d_in[1];
    const float* bq = (const float*)d_in[2];
    const float* wk = (const float*)d_in[3];
    const float* bk = (const float*)d_in[4];
    const float* wv = (const float*)d_in[5];
    const float* bv = (const float*)d_in[6];
    float* out = (float*)d_out;

    dim3 grid(16 * H_DIM);     // one CTA per (b,h)
    dim3 block(THREADS);
    fused_attn_kernel<<<grid, block>>>(x, wq, bq, wk, bk, wv, bv, out);
}